// round 9
// baseline (speedup 1.0000x reference)
#include <cuda_runtime.h>
#include <cstdint>

// Problem constants (from reference)
#define BER_F 0.02f
#define NBITS 9

#define NF 262144                  // 64*64*64 fine indices
#define NC 65536                   // 64*32*32 coarse indices
#define NTOT 327680
#define HWF 4096
#define HWC 1024
#define ROW4  163840u              // float4 per output batch row
#define ROWF4 131072u              // float4 fine part per row
#define DD4   32u                  // float4 per D=128 vector

#define TPB 64
#define IPB 64                     // indices per block; divides HWF and HWC rows
#define NBLK   (NTOT / IPB)        // 5120 blocks, exact
#define NBLK_F (NF / IPB)          // 4096 fine blocks

__device__ __forceinline__ unsigned smem_u32(const void* p) {
    return (unsigned)__cvta_generic_to_shared(p);
}

// Phase 1: compute rx for the block's 64 indices (coalesced staging, no
// ballot). Phase 2: fire-and-forget cp.async (LDGSTS) gathers codebook rows
// into smem — no register dependency on load data. Phase 3: one 32KB TMA
// bulk store smem->gmem (block output is exactly contiguous), removing all
// store wavefronts from L1tex and all STG issue cost.
__global__ __launch_bounds__(TPB)
void awgn_channel_kernel(const int* __restrict__ idx_c,
                         const int* __restrict__ idx_f,
                         const float4* __restrict__ cb_c,   // [512][32] float4
                         const float4* __restrict__ cb_f,   // [512][32] float4
                         const float* __restrict__ u_c,     // [NC][9]
                         const float* __restrict__ u_f,     // [NF][9]
                         float4* __restrict__ out)
{
    __shared__ float su[IPB * NBITS];                       // 2304 B
    __shared__ int   srx[IPB];                              // 256 B
    __shared__ __align__(16) unsigned char buf[IPB * 512];  // 32 KB gathered rows

    const unsigned tid = threadIdx.x;
    const bool fine = (blockIdx.x < NBLK_F);

    const float*  u;
    const int*    idxp;
    const float4* cb;
    unsigned gbase;   // base index within region
    unsigned obase;   // float4 offset of this block's first output vector
    if (fine) {
        gbase = blockIdx.x * IPB;
        u = u_f;  idxp = idx_f;  cb = cb_f;
        obase = (gbase >> 12) * ROW4 + (gbase & (HWF - 1)) * DD4;
    } else {
        gbase = blockIdx.x * IPB - NF;
        u = u_c;  idxp = idx_c;  cb = cb_c;
        obase = (gbase >> 10) * ROW4 + ROWF4 + (gbase & (HWC - 1)) * DD4;
    }

    // --- phase 1a: stage u coalesced (9 independent loads/thread) ---
    const float* ub = u + (size_t)gbase * NBITS;
    #pragma unroll
    for (int i = 0; i < NBITS; i++)
        su[tid + i * TPB] = ub[tid + i * TPB];

    const int myidx = idxp[gbase + tid];   // own idx, issued before barrier
    __syncthreads();

    // --- phase 1b: 9-bit flip mask; XOR of 9-bit values -> clip no-op ---
    unsigned m = 0;
    #pragma unroll
    for (int k = 0; k < NBITS; k++)
        m |= (su[tid * NBITS + k] < BER_F) ? (1u << k) : 0u;
    srx[tid] = (myidx ^ (int)m) & 511;
    __syncthreads();

    // --- phase 2: LDGSTS gather. Warp w handles rows [w*32, w*32+32).
    // Lane l copies bytes [l*16, l*16+16) of each 512B codebook row. ---
    const unsigned w = tid >> 5, lane = tid & 31;
    const float4* cbl = cb + lane;
    const unsigned sdst0 = smem_u32(buf) + (w * 32) * 512 + lane * 16;

    #pragma unroll
    for (int r = 0; r < 32; r++) {
        const float4* src = cbl + (unsigned)srx[w * 32 + r] * DD4;
        asm volatile("cp.async.ca.shared.global [%0], [%1], 16;"
                     :: "r"(sdst0 + r * 512), "l"(src));
    }
    asm volatile("cp.async.commit_group;");
    asm volatile("cp.async.wait_group 0;" ::: "memory");
    __syncthreads();

    // --- phase 3: single 32KB bulk store smem -> contiguous gmem region ---
    if (tid == 0) {
        asm volatile("fence.proxy.async.shared::cta;" ::: "memory");
        const float4* gdst = out + obase;
        asm volatile("cp.async.bulk.global.shared::cta.bulk_group [%0], [%1], %2;"
                     :: "l"(gdst), "r"(smem_u32(buf)), "r"(IPB * 512));
        asm volatile("cp.async.bulk.commit_group;");
        // Must not let the CTA release its smem while the bulk engine is
        // still reading it.
        asm volatile("cp.async.bulk.wait_group.read 0;" ::: "memory");
    }
}

extern "C" void kernel_launch(void* const* d_in, const int* in_sizes, int n_in,
                              void* d_out, int out_size)
{
    const int*    idx_c = (const int*)d_in[0];
    const int*    idx_f = (const int*)d_in[1];
    const float4* cb_c  = (const float4*)d_in[2];
    const float4* cb_f  = (const float4*)d_in[3];
    const float*  u_c   = (const float*)d_in[4];
    const float*  u_f   = (const float*)d_in[5];
    float4*       out   = (float4*)d_out;

    awgn_channel_kernel<<<NBLK, TPB>>>(idx_c, idx_f, cb_c, cb_f, u_c, u_f, out);
}

// round 15
// speedup vs baseline: 1.1487x; 1.1487x over previous
#include <cuda_runtime.h>

// Problem constants (from reference)
#define BER_F 0.02f
#define NBITS 9

#define NF 262144                  // 64*64*64 fine indices
#define NC 65536                   // 64*32*32 coarse indices
#define NTOT 327680
#define HWF 4096
#define HWC 1024
#define ROW4  163840u              // float4 per output batch row
#define ROWF4 131072u              // float4 fine part per row
#define DD4   32u                  // float4 per D=128 vector

#define TPB 128
#define IPB 128                    // indices per block (NF % IPB == 0)
#define NBLK   (NTOT / IPB)        // 2560 blocks, exact
#define NBLK_F (NF / IPB)          // 2048 fine blocks

// Two-phase (R6 design) + software-pipelined phase 2: double-buffered
// batches of 8 keep gathers continuously in flight while stores drain.
__global__ __launch_bounds__(TPB)
void awgn_channel_kernel(const int* __restrict__ idx_c,
                         const int* __restrict__ idx_f,
                         const float4* __restrict__ cb_c,   // [512][32] float4
                         const float4* __restrict__ cb_f,   // [512][32] float4
                         const float* __restrict__ u_c,     // [NC][9]
                         const float* __restrict__ u_f,     // [NF][9]
                         float4* __restrict__ out)
{
    __shared__ float su[IPB * NBITS];   // 4608 B staged uniforms
    __shared__ int   srx[IPB];          // received indices

    const unsigned tid = threadIdx.x;
    const bool fine = (blockIdx.x < NBLK_F);

    const float*  u;
    const int*    idxp;
    const float4* cb;
    unsigned gbase;   // base index within region
    unsigned obase;   // float4 offset of this block's first output vector
    if (fine) {
        gbase = blockIdx.x * IPB;
        u = u_f;  idxp = idx_f;  cb = cb_f;
        obase = (gbase >> 12) * ROW4 + (gbase & (HWF - 1)) * DD4;
    } else {
        gbase = blockIdx.x * IPB - NF;
        u = u_c;  idxp = idx_c;  cb = cb_c;
        obase = (gbase >> 10) * ROW4 + ROWF4 + (gbase & (HWC - 1)) * DD4;
    }

    // --- phase 1a: stage u coalesced (9 independent loads/thread) ---
    const float* ub = u + (size_t)gbase * NBITS;
    #pragma unroll
    for (int i = 0; i < NBITS; i++)
        su[tid + i * TPB] = ub[tid + i * TPB];

    const int myidx = idxp[gbase + tid];   // own idx, issued before barrier
    __syncthreads();

    // --- phase 1b: 9-bit flip mask; XOR of 9-bit values -> clip no-op ---
    unsigned m = 0;
    #pragma unroll
    for (int k = 0; k < NBITS; k++)
        m |= (su[tid * NBITS + k] < BER_F) ? (1u << k) : 0u;
    srx[tid] = (myidx ^ (int)m) & 511;
    __syncthreads();

    // --- phase 2: warp w copies indices [w*32, w*32+32), pipelined ---
    const unsigned w = tid >> 5, lane = tid & 31;
    const float4* cbl = cb + lane;
    float4* ol = out + obase + lane;
    const int* rxw = srx + w * 32;

    float4 va[8], vb[8];

    // gather batch t into dst (8 independent 512B LDG.128)
    #define GATHER(dst, t)                                              \
        _Pragma("unroll")                                               \
        for (int q = 0; q < 8; q++)                                     \
            dst[q] = __ldg(&cbl[(unsigned)rxw[(t) * 8 + q] * DD4]);
    // store batch t from src (streaming, never re-read)
    #define STORE(src, t)                                               \
        _Pragma("unroll")                                               \
        for (int q = 0; q < 8; q++)                                     \
            __stcs(&ol[(unsigned)(w * 32 + (t) * 8 + q) * DD4], src[q]);

    GATHER(va, 0);
    GATHER(vb, 1);  STORE(va, 0);
    GATHER(va, 2);  STORE(vb, 1);
    GATHER(vb, 3);  STORE(va, 2);
    STORE(vb, 3);

    #undef GATHER
    #undef STORE
}

extern "C" void kernel_launch(void* const* d_in, const int* in_sizes, int n_in,
                              void* d_out, int out_size)
{
    const int*    idx_c = (const int*)d_in[0];
    const int*    idx_f = (const int*)d_in[1];
    const float4* cb_c  = (const float4*)d_in[2];
    const float4* cb_f  = (const float4*)d_in[3];
    const float*  u_c   = (const float*)d_in[4];
    const float*  u_f   = (const float*)d_in[5];
    float4*       out   = (float4*)d_out;

    awgn_channel_kernel<<<NBLK, TPB>>>(idx_c, idx_f, cb_c, cb_f, u_c, u_f, out);
}